// round 14
// baseline (speedup 1.0000x reference)
#include <cuda_runtime.h>
#include <math.h>

#define NG 192
#define NTOT (NG * NG * NG)
#define BXT 32           // threads x (2 voxels each)
#define BYT 4
#define BZT 4
#define VX  64           // voxels per block in x
#define TX2 68           // tile cols (64 + 4 halo), even
#define TYH 8            // 4 + 4 (y halo +-2)
#define TZH 6            // 4 + 2 (z halo only +2: forward offsets)
#define NROWS (TYH * TZH)      // 48
#define TILE (NROWS * TX2)     // 3264 u32 ~ 13 KB

#define KN   500000.0f
#define MU   0.5f
#define EPSF 1e-4f
#define FULLMASK 0xffffffffu
#define BMASK 0x00FEFEFEu
#define LCAP (1 << 20)

// hit list + counter; statically zero; trailing reset kernel restores the
// zero invariant each run, so graph replays are deterministic.
__device__ int g_count;
__device__ int g_list[LCAP];

__device__ __forceinline__ int wrapN(int v) {
    if (v < 0) v += NG;
    if (v >= NG) v -= NG;
    return v;
}

// exact forward-offset check for one voxel; appends both endpoints of every
// true pair (d2 < two_d2, including d2 == 0 for friction) to the hit list.
__device__ __noinline__ void exact_forward_append(
    int gz, int gy, int gx, float two_d2,
    const float* __restrict__ xg, const float* __restrict__ yg,
    const float* __restrict__ zg)
{
    const int gidx = (gz * NG + gy) * NG + gx;
    const float px = xg[gidx], py = yg[gidx], pz = zg[gidx];
    #pragma unroll 1
    for (int oz = 0; oz <= 2; oz++) {
        #pragma unroll 1
        for (int oy = -2; oy <= 2; oy++) {
            if (oz == 0 && oy < 0) continue;
            #pragma unroll 1
            for (int ox = -2; ox <= 2; ox++) {
                if (oz == 0 && oy == 0 && ox < 1) continue;
                const int nidx = (wrapN(gz + oz) * NG + wrapN(gy + oy)) * NG
                               + wrapN(gx + ox);
                const float dx = px - xg[nidx];
                const float dy = py - yg[nidx];
                const float dz = pz - zg[nidx];
                const float d2 = fmaf(dz, dz, fmaf(dy, dy, dx * dx));
                if (d2 < two_d2) {
                    int i0 = atomicAdd(&g_count, 2);
                    if (i0 + 1 < LCAP) {
                        g_list[i0]     = gidx;
                        g_list[i0 + 1] = nidx;
                    }
                }
            }
        }
    }
}

// ---------------- Pass A: x-pair filter + zero-store + list append ----------
__global__ __launch_bounds__(BXT * BYT * BZT, 3)
void filter_kernel(const float* __restrict__ xg, const float* __restrict__ yg,
                   const float* __restrict__ zg,
                   const float* __restrict__ dptr, float* __restrict__ out)
{
    __shared__ __align__(8) unsigned qpk[TILE];

    const int lx = threadIdx.x, ly = threadIdx.y, lz = threadIdx.z;
    const int bx0 = blockIdx.x * VX;
    const int by0 = blockIdx.y * BYT;
    const int bz0 = blockIdx.z * BZT;
    const int tid  = (lz * BYT + ly) * BXT + lx;
    const int wid  = tid >> 5;
    const int lane = tid & 31;

    // --- halo key build: warp w loads rows 3w..3w+2; wrap math uniform/row --
    #pragma unroll 1
    for (int j = 0; j < 3; j++) {
        const int row = wid * 3 + j;          // 16 warps * 3 = 48 rows
        const int tz = row / TYH, ty = row % TYH;
        const int gz = wrapN(bz0 + tz);       // z halo: only above
        const int gy = wrapN(by0 + ty - 2);
        const float* rxp = xg + (gz * NG + gy) * NG;
        const float* ryp = yg + (gz * NG + gy) * NG;
        const float* rzp = zg + (gz * NG + gy) * NG;
        #pragma unroll
        for (int k = 0; k < 3; k++) {
            const int col = lane + 32 * k;
            if (col < TX2) {
                const int gxx = wrapN(bx0 + col - 2);
                qpk[row * TX2 + col] =
                    (unsigned)(int)rxp[gxx] | ((unsigned)(int)ryp[gxx] << 8)
                    | ((unsigned)(int)rzp[gxx] << 16);
            }
        }
    }
    __syncthreads();

    const float d      = *dptr;
    const float two_d  = 2.0f * d;
    const float two_d2 = two_d * two_d;
    const bool  filter_ok = (two_d <= 1.0f);

    // centers: cols cx0 = 2lx+2 and cx0+1, at row (lz, ly+2)
    const uint2* qp2 = (const uint2*)qpk;
    const int base2 = (lz * TYH + (ly + 2)) * (TX2 / 2) + lx;  // uint2 units
    const unsigned pq0 = qpk[(lz * TYH + (ly + 2)) * TX2 + 2 * lx + 2];
    const unsigned pq1 = qpk[(lz * TYH + (ly + 2)) * TX2 + 2 * lx + 3];

    unsigned a0 = ~0u, a1 = ~0u, a2 = ~0u, a3 = ~0u;   // voxel0 min-accs
    unsigned b0 = ~0u, b1 = ~0u, b2 = ~0u, b3 = ~0u;   // voxel1
    if (filter_ok) {
        #define TST(M, P, K) M = min(M, __vabsdiffu4(P, K) & BMASK)
        #pragma unroll
        for (int oz = 0; oz <= 2; oz++) {
            #pragma unroll
            for (int oy = -2; oy <= 2; oy++) {
                if (oz == 0 && oy < 0) continue;
                const int r2 = base2 + (oz * TYH + oy) * (TX2 / 2);
                const uint2 w0 = qp2[r2];
                const uint2 w1 = qp2[r2 + 1];
                const uint2 w2 = qp2[r2 + 2];
                const unsigned k0 = w0.x, k1 = w0.y, k2 = w1.x;
                const unsigned k3 = w1.y, k4 = w2.x, k5 = w2.y;
                if (oz == 0 && oy == 0) {
                    // partial row: v0 tests ox=1,2 (k3,k4); v1: k4,k5
                    TST(a0, pq0, k3); TST(a1, pq0, k4);
                    TST(b0, pq1, k4); TST(b1, pq1, k5);
                } else {
                    TST(a0, pq0, k0); TST(a1, pq0, k1); TST(a2, pq0, k2);
                    TST(a3, pq0, k3); TST(a0, pq0, k4);
                    TST(b0, pq1, k1); TST(b1, pq1, k2); TST(b2, pq1, k3);
                    TST(b3, pq1, k4); TST(b0, pq1, k5);
                }
            }
        }
        #undef TST
    }

    const bool need0 = !filter_ok || (min(min(a0, a1), min(a2, a3)) == 0u);
    const bool need1 = !filter_ok || (min(min(b0, b1), min(b2, b3)) == 0u);

    // zero all nine outputs (pairs are x-consecutive -> STG.64)
    const int gz = bz0 + lz, gy = by0 + ly, gx0 = bx0 + 2 * lx;
    const int gidx0 = (gz * NG + gy) * NG + gx0;
    const float2 z2 = make_float2(0.f, 0.f);
    #pragma unroll
    for (int q = 0; q < 9; q++)
        *(float2*)(out + q * NTOT + gidx0) = z2;

    // rare: exact forward check appends true pairs to the list
    if (__any_sync(FULLMASK, need0 || need1)) {
        if (need0) exact_forward_append(gz, gy, gx0,     two_d2, xg, yg, zg);
        if (need1) exact_forward_append(gz, gy, gx0 + 1, two_d2, xg, yg, zg);
    }
}

// ---------------- Pass B: WARP-per-voxel exact evaluation -------------------
#define FBLK 256
#define FGRD 128
__global__ __launch_bounds__(FBLK)
void fixup_kernel(const float* __restrict__ xg, const float* __restrict__ yg,
                  const float* __restrict__ zg, const float* __restrict__ vxg,
                  const float* __restrict__ vyg, const float* __restrict__ vzg,
                  const float* __restrict__ dptr, float* __restrict__ out,
                  float eta)
{
    const int n = min(g_count, LCAP);
    if (n == 0) return;
    const int lane  = threadIdx.x & 31;
    const int warp  = (blockIdx.x * FBLK + threadIdx.x) >> 5;
    const int nwarp = (FGRD * FBLK) >> 5;
    const float two_d  = 2.0f * (*dptr);
    const float two_d2 = two_d * two_d;

    for (int i = warp; i < n; i += nwarp) {
        const int v  = g_list[i];
        const int gx = v % NG;
        const int r  = v / NG;
        const int gy = r % NG;
        const int gz = r / NG;

        const float px = xg[v], py = yg[v], pz = zg[v];
        const float pvx = vxg[v], pvy = vyg[v], pvz = vzg[v];

        float fxc = 0.f, fyc = 0.f, fzc = 0.f;
        float fxd = 0.f, fyd = 0.f, fzd = 0.f;

        // lane l handles offsets l, l+32, l+64, l+96 of 125 (self excluded
        // by the d2 > 0 guard). Independent loads -> MLP.
        #pragma unroll
        for (int kk = 0; kk < 4; kk++) {
            const int k = lane + 32 * kk;
            if (k < 125) {
                const int oz = k / 25 - 2;
                const int oy = (k / 5) % 5 - 2;
                const int ox = k % 5 - 2;
                const int nidx = (wrapN(gz + oz) * NG + wrapN(gy + oy)) * NG
                               + wrapN(gx + ox);
                const float dx = px - xg[nidx];
                const float dy = py - yg[nidx];
                const float dz = pz - zg[nidx];
                const float d2 = fmaf(dz, dz, fmaf(dy, dy, dx * dx));
                if (d2 < two_d2 && d2 > 0.0f) {
                    const float dist = sqrtf(d2);
                    const float safe = fmaxf(EPSF, dist);
                    const float inv  = 1.0f / safe;
                    const float coef = KN * (dist - two_d) * inv;
                    fxc += coef * dx;
                    fyc += coef * dy;
                    fzc += coef * dz;
                    const float dvx = pvx - vxg[nidx];
                    const float dvy = pvy - vyg[nidx];
                    const float dvz = pvz - vzg[nidx];
                    const float vn  = (dvx * dx + dvy * dy + dvz * dz) * inv;
                    const float c2  = eta * vn * inv;
                    fxd += c2 * dx;
                    fyd += c2 * dy;
                    fzd += c2 * dz;
                }
            }
        }

        #pragma unroll
        for (int s = 16; s > 0; s >>= 1) {
            fxc += __shfl_xor_sync(FULLMASK, fxc, s);
            fyc += __shfl_xor_sync(FULLMASK, fyc, s);
            fzc += __shfl_xor_sync(FULLMASK, fzc, s);
            fxd += __shfl_xor_sync(FULLMASK, fxd, s);
            fyd += __shfl_xor_sync(FULLMASK, fyd, s);
            fzd += __shfl_xor_sync(FULLMASK, fzd, s);
        }

        if (lane == 0) {
            // friction: only the LAST scan shift s=(2,2,2) survives, i.e.
            // neighbor offset (-2,-2,-2), against the fully accumulated sums.
            float frx = 0.f, fry = 0.f, frz = 0.f;
            const int nidx = (wrapN(gz - 2) * NG + wrapN(gy - 2)) * NG
                           + wrapN(gx - 2);
            const float dx = px - xg[nidx];
            const float dy = py - yg[nidx];
            const float dz = pz - zg[nidx];
            const float d2 = fmaf(dz, dz, fmaf(dy, dy, dx * dx));
            if (d2 < two_d2) {
                const float dvx = pvx - vxg[nidx];
                const float dvy = pvy - vyg[nidx];
                const float dvz = pvz - vzg[nidx];
                frx = -(fabsf(fabsf(MU * fyc) + fabsf(MU * fzc) - MU * fxd)
                        * dvx / fmaxf(EPSF, fabsf(dvx)));
                fry = -(fabsf(fabsf(MU * fxc) + fabsf(MU * fzc) - MU * fyd)
                        * dvy / fmaxf(EPSF, fabsf(dvy)));
                // NB: reference uses diffvy in the z-friction numerator (kept).
                frz = -(fabsf(fabsf(MU * fxc) + fabsf(MU * fyc) - MU * fzd)
                        * dvy / fmaxf(EPSF, fabsf(dvz)));
            }
            float* o = out + v;
            o[0 * NTOT] = fxc;
            o[1 * NTOT] = fyc;
            o[2 * NTOT] = fzc;
            o[3 * NTOT] = fxd;
            o[4 * NTOT] = fyd;
            o[5 * NTOT] = fzd;
            o[6 * NTOT] = frx;
            o[7 * NTOT] = fry;
            o[8 * NTOT] = frz;
        }
    }
}

// ---------------- Pass C: restore counter invariant for graph replay --------
__global__ void reset_kernel() {
    g_count = 0;
}

extern "C" void kernel_launch(void* const* d_in, const int* in_sizes, int n_in,
                              void* d_out, int out_size)
{
    const float* xg   = (const float*)d_in[0];
    const float* yg   = (const float*)d_in[1];
    const float* zg   = (const float*)d_in[2];
    const float* vxg  = (const float*)d_in[3];
    const float* vyg  = (const float*)d_in[4];
    const float* vzg  = (const float*)d_in[5];
    const float* dptr = (const float*)d_in[6];
    float* out = (float*)d_out;

    // ETA = 2*gamma*sqrt(KN), gamma = alpha/sqrt(alpha^2+1), alpha = -ln(0.7)/pi
    const double alpha = -log(0.7) / M_PI;
    const double gam   = alpha / sqrt(alpha * alpha + 1.0);
    const float  eta   = (float)(2.0 * gam * sqrt(500000.0));

    dim3 blockA(BXT, BYT, BZT);
    dim3 gridA(NG / VX, NG / BYT, NG / BZT);
    filter_kernel<<<gridA, blockA>>>(xg, yg, zg, dptr, out);

    fixup_kernel<<<FGRD, FBLK>>>(xg, yg, zg, vxg, vyg, vzg, dptr, out, eta);

    reset_kernel<<<1, 1>>>();   // runs after fixup reads g_count
}

// round 15
// speedup vs baseline: 1.0500x; 1.0500x over previous
#include <cuda_runtime.h>
#include <math.h>

#define NG 192
#define NTOT (NG * NG * NG)
#define BXT 32           // threads x (2 voxels each)
#define BYT 4
#define BZT 4
#define VX  64           // voxels per block in x
#define TX2 68           // tile cols (64 + 4 halo), even
#define TYH 8            // 4 + 4 (y halo +-2)
#define TZH 6            // 4 + 2 (z halo only +2: forward offsets)
#define NROWS (TYH * TZH)      // 48
#define TILE (NROWS * TX2)     // 3264 u32 ~ 13 KB

#define KN   500000.0f
#define MU   0.5f
#define EPSF 1e-4f
#define FULLMASK 0xffffffffu
#define BMASK 0x00FEFEFEu
#define LCAP (1 << 20)

// hit list + counter; statically zero; trailing reset kernel restores the
// zero invariant each run, so graph replays are deterministic.
__device__ int g_count;
__device__ int g_list[LCAP];

__device__ __forceinline__ int wrapN(int v) {
    if (v < 0) v += NG;
    if (v >= NG) v -= NG;
    return v;
}

// exact forward-offset check for one voxel; appends both endpoints of every
// true pair (d2 < two_d2, including d2 == 0 for friction) to the hit list.
__device__ __noinline__ void exact_forward_append(
    int gz, int gy, int gx, float two_d2,
    const float* __restrict__ xg, const float* __restrict__ yg,
    const float* __restrict__ zg)
{
    const int gidx = (gz * NG + gy) * NG + gx;
    const float px = xg[gidx], py = yg[gidx], pz = zg[gidx];
    #pragma unroll 1
    for (int oz = 0; oz <= 2; oz++) {
        #pragma unroll 1
        for (int oy = -2; oy <= 2; oy++) {
            if (oz == 0 && oy < 0) continue;
            #pragma unroll 1
            for (int ox = -2; ox <= 2; ox++) {
                if (oz == 0 && oy == 0 && ox < 1) continue;
                const int nidx = (wrapN(gz + oz) * NG + wrapN(gy + oy)) * NG
                               + wrapN(gx + ox);
                const float dx = px - xg[nidx];
                const float dy = py - yg[nidx];
                const float dz = pz - zg[nidx];
                const float d2 = fmaf(dz, dz, fmaf(dy, dy, dx * dx));
                if (d2 < two_d2) {
                    int i0 = atomicAdd(&g_count, 2);
                    if (i0 + 1 < LCAP) {
                        g_list[i0]     = gidx;
                        g_list[i0 + 1] = nidx;
                    }
                }
            }
        }
    }
}

// ---------------- Pass A: x-pair filter + zero-store + list append ----------
// __launch_bounds__(512, 4): force 32 regs -> 4 resident blocks (R13 occupancy)
__global__ __launch_bounds__(BXT * BYT * BZT, 4)
void filter_kernel(const float* __restrict__ xg, const float* __restrict__ yg,
                   const float* __restrict__ zg,
                   const float* __restrict__ dptr, float* __restrict__ out)
{
    __shared__ __align__(8) unsigned qpk[TILE];

    const int lx = threadIdx.x, ly = threadIdx.y, lz = threadIdx.z;
    const int bx0 = blockIdx.x * VX;
    const int by0 = blockIdx.y * BYT;
    const int bz0 = blockIdx.z * BZT;
    const int tid  = (lz * BYT + ly) * BXT + lx;
    const int wid  = tid >> 5;
    const int lane = tid & 31;

    // --- halo key build: warp w loads rows 3w..3w+2; wrap math uniform/row --
    #pragma unroll 1
    for (int j = 0; j < 3; j++) {
        const int row = wid * 3 + j;          // 16 warps * 3 = 48 rows
        const int tz = row / TYH, ty = row % TYH;
        const int gz = wrapN(bz0 + tz);       // z halo: only above
        const int gy = wrapN(by0 + ty - 2);
        const float* rxp = xg + (gz * NG + gy) * NG;
        const float* ryp = yg + (gz * NG + gy) * NG;
        const float* rzp = zg + (gz * NG + gy) * NG;
        #pragma unroll
        for (int k = 0; k < 3; k++) {
            const int col = lane + 32 * k;
            if (col < TX2) {
                const int gxx = wrapN(bx0 + col - 2);
                qpk[row * TX2 + col] =
                    (unsigned)(int)rxp[gxx] | ((unsigned)(int)ryp[gxx] << 8)
                    | ((unsigned)(int)rzp[gxx] << 16);
            }
        }
    }
    __syncthreads();

    const float d      = *dptr;
    const float two_d  = 2.0f * d;
    const float two_d2 = two_d * two_d;
    const bool  filter_ok = (two_d <= 1.0f);

    // centers: cols cx0 = 2lx+2 and cx0+1, at row (lz, ly+2)
    const uint2* qp2 = (const uint2*)qpk;
    const int base2 = (lz * TYH + (ly + 2)) * (TX2 / 2) + lx;  // uint2 units
    const unsigned pq0 = qpk[(lz * TYH + (ly + 2)) * TX2 + 2 * lx + 2];
    const unsigned pq1 = qpk[(lz * TYH + (ly + 2)) * TX2 + 2 * lx + 3];

    unsigned a0 = ~0u, a1 = ~0u, a2 = ~0u, a3 = ~0u;   // voxel0 min-accs
    unsigned b0 = ~0u, b1 = ~0u, b2 = ~0u, b3 = ~0u;   // voxel1
    if (filter_ok) {
        #define TST(M, P, K) M = min(M, __vabsdiffu4(P, K) & BMASK)
        #pragma unroll
        for (int oz = 0; oz <= 2; oz++) {
            #pragma unroll
            for (int oy = -2; oy <= 2; oy++) {
                if (oz == 0 && oy < 0) continue;
                const int r2 = base2 + (oz * TYH + oy) * (TX2 / 2);
                const uint2 w0 = qp2[r2];
                const uint2 w1 = qp2[r2 + 1];
                const uint2 w2 = qp2[r2 + 2];
                const unsigned k0 = w0.x, k1 = w0.y, k2 = w1.x;
                const unsigned k3 = w1.y, k4 = w2.x, k5 = w2.y;
                if (oz == 0 && oy == 0) {
                    // partial row: v0 tests ox=1,2 (k3,k4); v1: k4,k5
                    TST(a0, pq0, k3); TST(a1, pq0, k4);
                    TST(b0, pq1, k4); TST(b1, pq1, k5);
                } else {
                    TST(a0, pq0, k0); TST(a1, pq0, k1); TST(a2, pq0, k2);
                    TST(a3, pq0, k3); TST(a0, pq0, k4);
                    TST(b0, pq1, k1); TST(b1, pq1, k2); TST(b2, pq1, k3);
                    TST(b3, pq1, k4); TST(b0, pq1, k5);
                }
            }
        }
        #undef TST
    }

    const bool need0 = !filter_ok || (min(min(a0, a1), min(a2, a3)) == 0u);
    const bool need1 = !filter_ok || (min(min(b0, b1), min(b2, b3)) == 0u);

    // zero all nine outputs (pairs are x-consecutive -> STG.64)
    const int gz = bz0 + lz, gy = by0 + ly, gx0 = bx0 + 2 * lx;
    const int gidx0 = (gz * NG + gy) * NG + gx0;
    const float2 z2 = make_float2(0.f, 0.f);
    #pragma unroll
    for (int q = 0; q < 9; q++)
        *(float2*)(out + q * NTOT + gidx0) = z2;

    // rare: exact forward check appends true pairs to the list
    if (__any_sync(FULLMASK, need0 || need1)) {
        if (need0) exact_forward_append(gz, gy, gx0,     two_d2, xg, yg, zg);
        if (need1) exact_forward_append(gz, gy, gx0 + 1, two_d2, xg, yg, zg);
    }
}

// ---------------- Pass B: WARP-per-voxel exact evaluation -------------------
#define FBLK 256
#define FGRD 128
__global__ __launch_bounds__(FBLK)
void fixup_kernel(const float* __restrict__ xg, const float* __restrict__ yg,
                  const float* __restrict__ zg, const float* __restrict__ vxg,
                  const float* __restrict__ vyg, const float* __restrict__ vzg,
                  const float* __restrict__ dptr, float* __restrict__ out,
                  float eta)
{
    const int n = min(g_count, LCAP);
    if (n == 0) return;
    const int lane  = threadIdx.x & 31;
    const int warp  = (blockIdx.x * FBLK + threadIdx.x) >> 5;
    const int nwarp = (FGRD * FBLK) >> 5;
    const float two_d  = 2.0f * (*dptr);
    const float two_d2 = two_d * two_d;

    for (int i = warp; i < n; i += nwarp) {
        const int v  = g_list[i];
        const int gx = v % NG;
        const int r  = v / NG;
        const int gy = r % NG;
        const int gz = r / NG;

        const float px = xg[v], py = yg[v], pz = zg[v];
        const float pvx = vxg[v], pvy = vyg[v], pvz = vzg[v];

        float fxc = 0.f, fyc = 0.f, fzc = 0.f;
        float fxd = 0.f, fyd = 0.f, fzd = 0.f;

        // lane l handles offsets l, l+32, l+64, l+96 of 125 (self excluded
        // by the d2 > 0 guard). Independent loads -> MLP.
        #pragma unroll
        for (int kk = 0; kk < 4; kk++) {
            const int k = lane + 32 * kk;
            if (k < 125) {
                const int oz = k / 25 - 2;
                const int oy = (k / 5) % 5 - 2;
                const int ox = k % 5 - 2;
                const int nidx = (wrapN(gz + oz) * NG + wrapN(gy + oy)) * NG
                               + wrapN(gx + ox);
                const float dx = px - xg[nidx];
                const float dy = py - yg[nidx];
                const float dz = pz - zg[nidx];
                const float d2 = fmaf(dz, dz, fmaf(dy, dy, dx * dx));
                if (d2 < two_d2 && d2 > 0.0f) {
                    const float dist = sqrtf(d2);
                    const float safe = fmaxf(EPSF, dist);
                    const float inv  = 1.0f / safe;
                    const float coef = KN * (dist - two_d) * inv;
                    fxc += coef * dx;
                    fyc += coef * dy;
                    fzc += coef * dz;
                    const float dvx = pvx - vxg[nidx];
                    const float dvy = pvy - vyg[nidx];
                    const float dvz = pvz - vzg[nidx];
                    const float vn  = (dvx * dx + dvy * dy + dvz * dz) * inv;
                    const float c2  = eta * vn * inv;
                    fxd += c2 * dx;
                    fyd += c2 * dy;
                    fzd += c2 * dz;
                }
            }
        }

        #pragma unroll
        for (int s = 16; s > 0; s >>= 1) {
            fxc += __shfl_xor_sync(FULLMASK, fxc, s);
            fyc += __shfl_xor_sync(FULLMASK, fyc, s);
            fzc += __shfl_xor_sync(FULLMASK, fzc, s);
            fxd += __shfl_xor_sync(FULLMASK, fxd, s);
            fyd += __shfl_xor_sync(FULLMASK, fyd, s);
            fzd += __shfl_xor_sync(FULLMASK, fzd, s);
        }

        if (lane == 0) {
            // friction: only the LAST scan shift s=(2,2,2) survives, i.e.
            // neighbor offset (-2,-2,-2), against the fully accumulated sums.
            float frx = 0.f, fry = 0.f, frz = 0.f;
            const int nidx = (wrapN(gz - 2) * NG + wrapN(gy - 2)) * NG
                           + wrapN(gx - 2);
            const float dx = px - xg[nidx];
            const float dy = py - yg[nidx];
            const float dz = pz - zg[nidx];
            const float d2 = fmaf(dz, dz, fmaf(dy, dy, dx * dx));
            if (d2 < two_d2) {
                const float dvx = pvx - vxg[nidx];
                const float dvy = pvy - vyg[nidx];
                const float dvz = pvz - vzg[nidx];
                frx = -(fabsf(fabsf(MU * fyc) + fabsf(MU * fzc) - MU * fxd)
                        * dvx / fmaxf(EPSF, fabsf(dvx)));
                fry = -(fabsf(fabsf(MU * fxc) + fabsf(MU * fzc) - MU * fyd)
                        * dvy / fmaxf(EPSF, fabsf(dvy)));
                // NB: reference uses diffvy in the z-friction numerator (kept).
                frz = -(fabsf(fabsf(MU * fxc) + fabsf(MU * fyc) - MU * fzd)
                        * dvy / fmaxf(EPSF, fabsf(dvz)));
            }
            float* o = out + v;
            o[0 * NTOT] = fxc;
            o[1 * NTOT] = fyc;
            o[2 * NTOT] = fzc;
            o[3 * NTOT] = fxd;
            o[4 * NTOT] = fyd;
            o[5 * NTOT] = fzd;
            o[6 * NTOT] = frx;
            o[7 * NTOT] = fry;
            o[8 * NTOT] = frz;
        }
    }
}

// ---------------- Pass C: restore counter invariant for graph replay --------
__global__ void reset_kernel() {
    g_count = 0;
}

extern "C" void kernel_launch(void* const* d_in, const int* in_sizes, int n_in,
                              void* d_out, int out_size)
{
    const float* xg   = (const float*)d_in[0];
    const float* yg   = (const float*)d_in[1];
    const float* zg   = (const float*)d_in[2];
    const float* vxg  = (const float*)d_in[3];
    const float* vyg  = (const float*)d_in[4];
    const float* vzg  = (const float*)d_in[5];
    const float* dptr = (const float*)d_in[6];
    float* out = (float*)d_out;

    // ETA = 2*gamma*sqrt(KN), gamma = alpha/sqrt(alpha^2+1), alpha = -ln(0.7)/pi
    const double alpha = -log(0.7) / M_PI;
    const double gam   = alpha / sqrt(alpha * alpha + 1.0);
    const float  eta   = (float)(2.0 * gam * sqrt(500000.0));

    dim3 blockA(BXT, BYT, BZT);
    dim3 gridA(NG / VX, NG / BYT, NG / BZT);
    filter_kernel<<<gridA, blockA>>>(xg, yg, zg, dptr, out);

    fixup_kernel<<<FGRD, FBLK>>>(xg, yg, zg, vxg, vyg, vzg, dptr, out, eta);

    reset_kernel<<<1, 1>>>();   // runs after fixup reads g_count
}